// round 9
// baseline (speedup 1.0000x reference)
#include <cuda_runtime.h>
#include <math.h>

#define BB 16
#define Nn 38
#define NTt 9
#define NEe 703
#define Rr 741
#define BRr (BB*Rr)
#define Ll 12
#define EROWS (BB*NEe)   // 11248
#define NROWS (BB*Nn)    // 608
#define TAU 0.004f

typedef unsigned long long ull;

// ---------------- static device scratch ----------------
__device__ __align__(16) float  g_PS1[BB*Nn*384];
__device__ __align__(16) float  g_W2T[128*384];
__device__ __align__(16) float  g_W3T[128*384];
__device__ __align__(16) float  g_EW1T[Ll*384*128];  // [l][o][c]
__device__ __align__(16) float  g_NW1T[Ll*128*128];  // [l][o][c]
__device__ __align__(16) double g_Sd[BRr*128];
__device__ __align__(16) float  g_sel2[BB*NEe*2*128];
__device__ double g_sum[128];
__device__ double g_sumsq[128];
__device__ double g_a[128];
__device__ double g_c0[128];
__device__ int    g_mode;

__device__ __forceinline__ bool read_mask(const void* p, int i, int mode) {
    if (mode == 0) return ((const unsigned char*)p)[i] != 0;
    if (mode == 1) return ((const float*)p)[i] != 0.0f;
    return ((const int*)p)[i] != 0;
}

// ---- packed f32x2 helpers (lane-wise rounding identical to scalar FFMA) ----
__device__ __forceinline__ ull pack2(float a, float b) {
    ull r; asm("mov.b64 %0, {%1, %2};" : "=l"(r) : "f"(a), "f"(b)); return r;
}
__device__ __forceinline__ void unpack2(ull v, float& x, float& y) {
    asm("mov.b64 {%0, %1}, %2;" : "=f"(x), "=f"(y) : "l"(v));
}
__device__ __forceinline__ void fma2(ull& d, ull a, ull b) {
    asm("fma.rn.f32x2 %0, %1, %2, %3;" : "=l"(d) : "l"(a), "l"(b), "l"(d));
}
__device__ __forceinline__ float f4c(const float4& v, int i) {
    return i == 0 ? v.x : (i == 1 ? v.y : (i == 2 ? v.z : v.w));
}

__global__ void k_init(const unsigned char* __restrict__ mn) {
    int t = threadIdx.x;
    if (t < 128) { g_sum[t] = 0.0; g_sumsq[t] = 0.0; }
    if (t == 0) {
        bool b8 = false, f32 = false;
        for (int i = 0; i < 152; i++) {
            unsigned char v = mn[i];
            if ((i & 3) != 0 && v == 1) b8 = true;
            if ((i & 3) == 3 && v == 0x3f) f32 = true;
        }
        g_mode = b8 ? 0 : (f32 ? 1 : 2);
    }
}

__global__ void k_prep_w(const float* __restrict__ gc2, const float* __restrict__ gc3,
                         const float* __restrict__ ew1, const float* __restrict__ nw1) {
    int i = blockIdx.x * 256 + threadIdx.x;
    if (i < 49152) {
        int k = i / 384, c = i % 384;
        g_W2T[i] = gc2[c*128 + k];
        g_W3T[i] = gc3[c*128 + k];
    }
    if (i < 589824) {
        int l = i / 49152, rem = i % 49152;
        int o = rem / 128, c = rem % 128;
        g_EW1T[i] = ew1[l*49152 + c*384 + o];
    }
    if (i < 196608) {
        int l = i / 16384, rem = i % 16384;
        int o = rem / 128, c = rem % 128;
        g_NW1T[i] = nw1[l*16384 + c*128 + o];
    }
}

__global__ void k_prep_ps1(const float* __restrict__ x, const float* __restrict__ embw,
                           const float* __restrict__ gc1) {
    __shared__ float h0[Nn*NTt];
    int b = blockIdx.x, t = threadIdx.x;
    if (t < Nn*NTt) {
        int j = t / NTt, tt = t % NTt;
        float acc = 0.f;
        #pragma unroll
        for (int u = 0; u < NTt; u++) acc += x[(b*Nn + j)*NTt + u] * embw[tt*NTt + u];
        h0[t] = acc;
    }
    __syncthreads();
    if (t < 384) {
        for (int j = 0; j < Nn; j++) {
            float acc = 0.f;
            #pragma unroll
            for (int u = 0; u < NTt; u++) acc += h0[j*NTt + u] * gc1[t*NTt + u];
            g_PS1[(b*Nn + j)*384 + t] = acc;
        }
    }
}

// ---------------- fused RGCN v4: per-e gemm+einsum fusion, 59KB smem, 3 CTAs/SM --------
// einsum partial: acc[r] += sum_j sA_e[row][j] * sE[j][col2]   (j ascending; e outer loop)
__device__ __forceinline__ void einsum_e(ull* acc, const float* __restrict__ aE,
                                         const float* __restrict__ sE,
                                         int tx, int rg, int cg) {
    const float* sp = sE + cg*64 + tx*2;
    const float* ap = aE + rg*10*40;
    #pragma unroll 2
    for (int j = 0; j < 40; j += 2) {
        float2 a2[10];
        #pragma unroll
        for (int r = 0; r < 10; r++) a2[r] = *(const float2*)(ap + r*40 + j);
        ull s0 = *(const ull*)(sp + j*128);
        ull s1 = *(const ull*)(sp + (j+1)*128);
        #pragma unroll
        for (int r = 0; r < 10; r++) fma2(acc[r], pack2(a2[r].x, a2[r].x), s0);
        #pragma unroll
        for (int r = 0; r < 10; r++) fma2(acc[r], pack2(a2[r].y, a2[r].y), s1);
    }
}

// gemm slice: sE[j][c] = sum_k sH[j][k] * WTe[k*384 + c]   (k ascending; WTe = WT + e*128)
__device__ __forceinline__ void gemm_e(const float* __restrict__ WTe,
                                       const float* __restrict__ sH,
                                       float* __restrict__ sE,
                                       int tx, int rg, int cg) {
    const float* wb = WTe + cg*64 + tx*2;
    const float* hb = sH + rg*10*128;
    ull acc[10];
    #pragma unroll
    for (int r = 0; r < 10; r++) acc[r] = 0ull;
    #pragma unroll 2
    for (int k = 0; k < 128; k += 2) {
        float2 h2[10];
        #pragma unroll
        for (int r = 0; r < 10; r++) h2[r] = *(const float2*)(hb + r*128 + k);
        ull w0 = *(const ull*)(wb + k*384);
        ull w1 = *(const ull*)(wb + (k+1)*384);
        #pragma unroll
        for (int r = 0; r < 10; r++) fma2(acc[r], pack2(h2[r].x, h2[r].x), w0);
        #pragma unroll
        for (int r = 0; r < 10; r++) fma2(acc[r], pack2(h2[r].y, h2[r].y), w1);
    }
    #pragma unroll
    for (int r = 0; r < 10; r++)
        *(ull*)(sE + (rg*10 + r)*128 + cg*64 + tx*2) = acc[r];
}

__device__ __forceinline__ void store_sH(const ull* acc, float* __restrict__ sH,
                                         int tx, int rg, int cg, bool relu) {
    #pragma unroll
    for (int r = 0; r < 10; r++) {
        float vx, vy;
        unpack2(acc[r], vx, vy);
        if (relu) { vx = fmaxf(vx, 0.f); vy = fmaxf(vy, 0.f); }
        *(ull*)(sH + (rg*10 + r)*128 + cg*64 + tx*2) = pack2(vx, vy);
    }
}

__global__ __launch_bounds__(256, 3) void k_rgcn(
    const float* __restrict__ adj, const void* __restrict__ maskn,
    const void* __restrict__ maske, const int* __restrict__ isel)
{
    extern __shared__ float sm[];
    float* sA = sm;            // 3*40*40 = 4800
    float* sH = sm + 4800;     // 40*128 = 5120
    float* sE = sm + 9920;     // 40*128 = 5120   (total 15040 floats = 58.75KB)
    int tid = threadIdx.x;
    int b = blockIdx.x / Rr, r = blockIdx.x % Rr;
    int mode = g_mode;

    for (int idx = tid; idx < 3*40*40; idx += 256) {
        int j = idx % 40;
        int i = (idx / 40) % 40;
        int e = idx / 1600;
        float v = 0.f;
        if (i < Nn && j < Nn && read_mask(maske, r*1444 + i*38 + j, mode))
            v = adj[((b*4 + e)*38 + i)*38 + j];
        sA[idx] = v;
    }

    int tx = tid & 31, ty = tid >> 5;
    int rg = ty >> 1, cg = ty & 1;

    // ---- layer 1: einsum over masked PS1 e-slices ----
    ull acc1[10];
    #pragma unroll
    for (int q = 0; q < 10; q++) acc1[q] = 0ull;
    for (int e = 0; e < 3; e++) {
        __syncthreads();   // sA ready (e=0) / prior einsum done reading sE (e>0)
        for (int idx = tid; idx < 40*128; idx += 256) {
            int j = idx >> 7, c = idx & 127;
            float v = 0.f;
            if (j < Nn && read_mask(maskn, r*38 + j, mode))
                v = g_PS1[(b*Nn + j)*384 + e*128 + c];
            sE[idx] = v;
        }
        __syncthreads();
        einsum_e(acc1, sA + e*1600, sE, tx, rg, cg);
    }
    store_sH(acc1, sH, tx, rg, cg, true);

    // ---- layer 2 ----
    ull acc2[10];
    #pragma unroll
    for (int q = 0; q < 10; q++) acc2[q] = 0ull;
    for (int e = 0; e < 3; e++) {
        __syncthreads();   // sH stores visible (e=0) / prior einsum done with sE (e>0)
        gemm_e(g_W2T + e*128, sH, sE, tx, rg, cg);
        __syncthreads();
        einsum_e(acc2, sA + e*1600, sE, tx, rg, cg);
    }
    store_sH(acc2, sH, tx, rg, cg, true);   // all gemm reads of sH completed before this

    // ---- layer 3 ----
    ull acc3[10];
    #pragma unroll
    for (int q = 0; q < 10; q++) acc3[q] = 0ull;
    for (int e = 0; e < 3; e++) {
        __syncthreads();
        gemm_e(g_W3T + e*128, sH, sE, tx, rg, cg);
        __syncthreads();
        einsum_e(acc3, sA + e*1600, sE, tx, rg, cg);
    }
    store_sH(acc3, sH, tx, rg, cg, false);
    __syncthreads();

    if (tid < 128) {
        double s = 0.0, sq = 0.0;
        for (int i = 0; i < Nn; i++) {
            double v = (double)sH[i*128 + tid];
            s += v; sq += v*v;
        }
        g_Sd[blockIdx.x*128 + tid] = s;
        atomicAdd(&g_sum[tid], s);
        atomicAdd(&g_sumsq[tid], sq);
    }
    if (r >= Nn) {
        int k = r - Nn;
        int o = tid & 127, sl = tid >> 7;
        int node = isel[k*2 + sl];
        g_sel2[((b*NEe + k)*2 + sl)*128 + o] = sH[node*128 + o];
    }
}

__global__ void k_stats(const float* __restrict__ gamma, const float* __restrict__ beta) {
    int o = threadIdx.x;
    if (o < 128) {
        const double cnt = (double)(BRr * Nn);
        double m   = g_sum[o] / cnt;
        double var = g_sumsq[o] / cnt - m*m;
        double inv = 1.0 / sqrt(var + 1e-5);
        double a = inv * (double)gamma[o];
        g_a[o]  = a;
        g_c0[o] = (double)beta[o] - m * a;
    }
}

// ---------------- flow kernels: fp32 fast path + fp64 fallback on small gaps ----------------
__global__ __launch_bounds__(256) void k_edge_flow(
    const float* __restrict__ adj_deq, const float* __restrict__ eb1,
    const float* __restrict__ ew2, const float* __restrict__ eb2,
    float* __restrict__ out)
{
    extern __shared__ float fsm[];
    float* sg = fsm;               // 32*384
    float* wt = fsm + 12288;       // 64*128
    float* h  = fsm + 20480;       // 32*128
    float* lg = fsm + 24576;       // 32*4
    int* bi    = (int*)(fsm + 24704);
    int* P     = bi + 32;
    int* flags = bi + 64;
    int tid = threadIdx.x;
    int row0 = blockIdx.x * 32;

    for (int idx = tid; idx < 32*384; idx += 256) {
        int rl = idx / 384, o = idx % 384;
        int row = row0 + rl;
        double v = 0.0;
        if (row < EROWS) {
            int b = row / NEe, k = row % NEe;
            if (o < 256) {
                int oo = o & 127;
                v = (double)g_sel2[(b*NEe + k)*256 + o] * g_a[oo] + g_c0[oo];
            } else {
                int oo = o - 256;
                v = g_Sd[(b*Rr + Nn + k)*128 + oo] * g_a[oo] + 38.0 * g_c0[oo];
            }
        }
        sg[idx] = (float)v;
    }
    if (tid < 32) P[tid] = 0;

    int wrp = tid >> 5, lane = tid & 31;
    int rbase = wrp * 4;
    for (int l = 0; l < Ll; l++) {
        ull acc[4][2];
        {
            float b0 = eb1[l*128 + lane*4+0], b1 = eb1[l*128 + lane*4+1];
            float b2 = eb1[l*128 + lane*4+2], b3 = eb1[l*128 + lane*4+3];
            ull p01 = pack2(b0, b1), p23 = pack2(b2, b3);
            #pragma unroll
            for (int r = 0; r < 4; r++) { acc[r][0] = p01; acc[r][1] = p23; }
        }
        for (int tile = 0; tile < 6; tile++) {
            __syncthreads();
            const float* src = g_EW1T + l*49152 + tile*8192;
            for (int i = tid*4; i < 8192; i += 1024)
                *(float4*)(wt + i) = *(const float4*)(src + i);
            __syncthreads();
            #pragma unroll 2
            for (int oo = 0; oo < 64; oo += 4) {
                float4 s4[4];
                #pragma unroll
                for (int r = 0; r < 4; r++)
                    s4[r] = *(const float4*)(sg + (rbase + r)*384 + tile*64 + oo);
                #pragma unroll
                for (int doo = 0; doo < 4; doo++) {
                    ulonglong2 w2 = *(const ulonglong2*)(wt + (oo + doo)*128 + lane*4);
                    #pragma unroll
                    for (int r = 0; r < 4; r++) {
                        float sv = f4c(s4[r], doo);
                        ull ss = pack2(sv, sv);
                        fma2(acc[r][0], ss, w2.x);
                        fma2(acc[r][1], ss, w2.y);
                    }
                }
            }
        }
        #pragma unroll
        for (int r = 0; r < 4; r++) {
            float a0, a1, a2, a3;
            unpack2(acc[r][0], a0, a1);
            unpack2(acc[r][1], a2, a3);
            float* hp = h + (rbase + r)*128 + lane*4;
            hp[0] = tanhf(a0); hp[1] = tanhf(a1); hp[2] = tanhf(a2); hp[3] = tanhf(a3);
        }
        __syncthreads();
        if (tid < 128) {
            int rl = tid >> 2, t = tid & 3;
            const float* W2 = ew2 + (l*4 + t)*128;
            float a = eb2[l*4 + t];
            for (int c = 0; c < 128; c++) a = fmaf(h[rl*128 + c], W2[c], a);
            lg[rl*4 + t] = a;
        }
        __syncthreads();
        if (tid < 32) {
            float l0 = lg[tid*4], l1 = lg[tid*4+1], l2 = lg[tid*4+2], l3 = lg[tid*4+3];
            float best = l0; int bx = 0;
            if (l1 > best) { best = l1; bx = 1; }
            if (l2 > best) { best = l2; bx = 2; }
            if (l3 > best) { best = l3; bx = 3; }
            float second = -1e30f;
            if (bx != 0 && l0 > second) second = l0;
            if (bx != 1 && l1 > second) second = l1;
            if (bx != 2 && l2 > second) second = l2;
            if (bx != 3 && l3 > second) second = l3;
            bi[tid] = bx;
            flags[tid] = (best - second < TAU) && (row0 + tid < EROWS);
        }
        __syncthreads();
        for (int r = 0; r < 4; r++) {
            int rl = rbase + r;
            if (!flags[rl]) continue;
            int row = row0 + rl;
            int b = row / NEe, k = row % NEe;
            const float* W1 = g_EW1T + l*49152;
            double accd[4];
            #pragma unroll
            for (int q = 0; q < 4; q++) accd[q] = (double)eb1[l*128 + lane + 32*q];
            for (int o = 0; o < 384; o++) {
                double gv;
                if (o < 256) {
                    int oo = o & 127;
                    gv = (double)g_sel2[(b*NEe + k)*256 + o] * g_a[oo] + g_c0[oo];
                } else {
                    int oo = o - 256;
                    gv = g_Sd[(b*Rr + Nn + k)*128 + oo] * g_a[oo] + 38.0 * g_c0[oo];
                }
                #pragma unroll
                for (int q = 0; q < 4; q++)
                    accd[q] = fma(gv, (double)W1[o*128 + lane + 32*q], accd[q]);
            }
            double hd[4];
            #pragma unroll
            for (int q = 0; q < 4; q++) hd[q] = tanh(accd[q]);
            double lgd[4];
            #pragma unroll
            for (int t = 0; t < 4; t++) {
                const float* W2 = ew2 + (l*4 + t)*128;
                double p = 0.0;
                #pragma unroll
                for (int q = 0; q < 4; q++) p = fma(hd[q], (double)W2[lane + 32*q], p);
                #pragma unroll
                for (int s = 16; s > 0; s >>= 1) p += __shfl_down_sync(0xffffffffu, p, s);
                lgd[t] = p;
            }
            if (lane == 0) {
                #pragma unroll
                for (int t = 0; t < 4; t++) lgd[t] += (double)eb2[l*4 + t];
                double best = lgd[0]; int bx = 0;
                if (lgd[1] > best) { best = lgd[1]; bx = 1; }
                if (lgd[2] > best) { best = lgd[2]; bx = 2; }
                if (lgd[3] > best) { best = lgd[3]; bx = 3; }
                bi[rl] = bx;
            }
        }
        __syncthreads();
        if (tid < 32) P[tid] += bi[tid];
    }
    __syncthreads();
    if (tid < 128) {
        int rl = tid >> 2, j = tid & 3;
        int row = row0 + rl;
        if (row < EROWS) {
            int p = P[rl] & 3;
            out[NROWS*NTt + row*4 + j] = adj_deq[row*4 + ((j - p + 4) & 3)];
        }
    }
}

__global__ __launch_bounds__(256) void k_node_flow(
    const float* __restrict__ x_deq, const float* __restrict__ nb1,
    const float* __restrict__ nw2, const float* __restrict__ nb2,
    float* __restrict__ out)
{
    extern __shared__ float fsm[];
    float* sg = fsm;               // 32*128
    float* wt = fsm + 4096;        // 64*128
    float* h  = fsm + 12288;       // 32*128
    float* lg = fsm + 16384;       // 32*9
    int* bi    = (int*)(fsm + 16672);
    int* P     = bi + 32;
    int* flags = bi + 64;
    int tid = threadIdx.x;
    int row0 = blockIdx.x * 32;

    for (int idx = tid; idx < 32*128; idx += 256) {
        int rl = idx >> 7, o = idx & 127;
        int row = row0 + rl;
        int b = row / Nn, n = row % Nn;
        sg[idx] = (float)(g_Sd[(b*Rr + n)*128 + o] * g_a[o] + 38.0 * g_c0[o]);
    }
    if (tid < 32) P[tid] = 0;

    int wrp = tid >> 5, lane = tid & 31;
    int rbase = wrp * 4;
    for (int l = 0; l < Ll; l++) {
        float acc[4][4];
        #pragma unroll
        for (int q = 0; q < 4; q++) {
            float bq = nb1[l*128 + lane*4 + q];
            acc[0][q] = bq; acc[1][q] = bq; acc[2][q] = bq; acc[3][q] = bq;
        }
        for (int tile = 0; tile < 2; tile++) {
            __syncthreads();
            const float* src = g_NW1T + l*16384 + tile*8192;
            for (int i = tid*4; i < 8192; i += 1024)
                *(float4*)(wt + i) = *(const float4*)(src + i);
            __syncthreads();
            #pragma unroll 2
            for (int oo = 0; oo < 64; oo++) {
                float4 w4 = *(const float4*)(wt + oo*128 + lane*4);
                #pragma unroll
                for (int r = 0; r < 4; r++) {
                    float s = sg[(rbase + r)*128 + tile*64 + oo];
                    acc[r][0] = fmaf(s, w4.x, acc[r][0]);
                    acc[r][1] = fmaf(s, w4.y, acc[r][1]);
                    acc[r][2] = fmaf(s, w4.z, acc[r][2]);
                    acc[r][3] = fmaf(s, w4.w, acc[r][3]);
                }
            }
        }
        #pragma unroll
        for (int r = 0; r < 4; r++)
            #pragma unroll
            for (int q = 0; q < 4; q++)
                h[(rbase + r)*128 + lane*4 + q] = tanhf(acc[r][q]);
        __syncthreads();
        for (int pp = tid; pp < 32*NTt; pp += 256) {
            int rl = pp / NTt, t = pp % NTt;
            const float* W2 = nw2 + (l*NTt + t)*128;
            float a = nb2[l*NTt + t];
            for (int c = 0; c < 128; c++) a = fmaf(h[rl*128 + c], W2[c], a);
            lg[rl*NTt + t] = a;
        }
        __syncthreads();
        if (tid < 32) {
            float best = lg[tid*NTt]; int bx = 0;
            #pragma unroll
            for (int t = 1; t < NTt; t++) {
                float v = lg[tid*NTt + t];
                if (v > best) { best = v; bx = t; }
            }
            float second = -1e30f;
            #pragma unroll
            for (int t = 0; t < NTt; t++) {
                float v = lg[tid*NTt + t];
                if (t != bx && v > second) second = v;
            }
            bi[tid] = bx;
            flags[tid] = (best - second < TAU);
        }
        __syncthreads();
        for (int r = 0; r < 4; r++) {
            int rl = rbase + r;
            if (!flags[rl]) continue;
            int row = row0 + rl;
            int b = row / Nn, n = row % Nn;
            const float* W1 = g_NW1T + l*16384;
            double accd[4];
            #pragma unroll
            for (int q = 0; q < 4; q++) accd[q] = (double)nb1[l*128 + lane + 32*q];
            for (int o = 0; o < 128; o++) {
                double gv = g_Sd[(b*Rr + n)*128 + o] * g_a[o] + 38.0 * g_c0[o];
                #pragma unroll
                for (int q = 0; q < 4; q++)
                    accd[q] = fma(gv, (double)W1[o*128 + lane + 32*q], accd[q]);
            }
            double hd[4];
            #pragma unroll
            for (int q = 0; q < 4; q++) hd[q] = tanh(accd[q]);
            double best = -1e300; int bx = 0;
            for (int t = 0; t < NTt; t++) {
                const float* W2 = nw2 + (l*NTt + t)*128;
                double p = 0.0;
                #pragma unroll
                for (int q = 0; q < 4; q++) p = fma(hd[q], (double)W2[lane + 32*q], p);
                #pragma unroll
                for (int s = 16; s > 0; s >>= 1) p += __shfl_down_sync(0xffffffffu, p, s);
                if (lane == 0) {
                    p += (double)nb2[l*NTt + t];
                    if (p > best) { best = p; bx = t; }
                }
            }
            if (lane == 0) bi[rl] = bx;
        }
        __syncthreads();
        if (tid < 32) P[tid] += bi[tid];
    }
    __syncthreads();
    for (int pp = tid; pp < 32*NTt; pp += 256) {
        int rl = pp / NTt, j = pp % NTt;
        int row = row0 + rl;
        int p = P[rl] % NTt;
        out[row*NTt + j] = x_deq[row*NTt + ((j - p + 18) % NTt)];
    }
}

extern "C" void kernel_launch(void* const* d_in, const int* in_sizes, int n_in,
                              void* d_out, int out_size) {
    const float* x       = (const float*)d_in[0];
    const float* adj     = (const float*)d_in[1];
    const float* x_deq   = (const float*)d_in[2];
    const float* adj_deq = (const float*)d_in[3];
    const void*  mn      = d_in[4];
    const void*  me      = d_in[5];
    const int*   isel    = (const int*)d_in[6];
    const float* embw    = (const float*)d_in[7];
    const float* gc1     = (const float*)d_in[8];
    const float* gc2     = (const float*)d_in[9];
    const float* gc3     = (const float*)d_in[10];
    const float* gamma   = (const float*)d_in[11];
    const float* beta    = (const float*)d_in[12];
    const float* nw1     = (const float*)d_in[13];
    const float* nb1     = (const float*)d_in[14];
    const float* nw2     = (const float*)d_in[15];
    const float* nb2     = (const float*)d_in[16];
    const float* ew1     = (const float*)d_in[17];
    const float* eb1     = (const float*)d_in[18];
    const float* ew2     = (const float*)d_in[19];
    const float* eb2     = (const float*)d_in[20];
    float* out = (float*)d_out;

    cudaFuncSetAttribute(k_rgcn, cudaFuncAttributeMaxDynamicSharedMemorySize, 61440);
    cudaFuncSetAttribute(k_edge_flow, cudaFuncAttributeMaxDynamicSharedMemorySize, 99200);
    cudaFuncSetAttribute(k_node_flow, cudaFuncAttributeMaxDynamicSharedMemorySize, 67072);

    k_init<<<1, 128>>>((const unsigned char*)mn);
    k_prep_w<<<2304, 256>>>(gc2, gc3, ew1, nw1);
    k_prep_ps1<<<16, 384>>>(x, embw, gc1);
    k_rgcn<<<BRr, 256, 60160>>>(adj, mn, me, isel);
    k_stats<<<1, 128>>>(gamma, beta);
    k_node_flow<<<19, 256, 67072>>>(x_deq, nb1, nw2, nb2, out);
    k_edge_flow<<<352, 256, 99200>>>(adj_deq, eb1, ew2, eb2, out);
}

// round 10
// speedup vs baseline: 1.2034x; 1.2034x over previous
#include <cuda_runtime.h>
#include <math.h>

#define BB 16
#define Nn 38
#define NTt 9
#define NEe 703
#define Rr 741
#define BRr (BB*Rr)
#define Ll 12
#define EROWS (BB*NEe)   // 11248
#define NROWS (BB*Nn)    // 608
#define EBLKS 352
#define TAU 0.0015f

typedef unsigned long long ull;

// ---------------- static device scratch ----------------
__device__ __align__(16) float  g_PS1[BB*Nn*384];
__device__ __align__(16) float  g_W2T[128*384];
__device__ __align__(16) float  g_W3T[128*384];
__device__ __align__(16) float  g_EW1T[Ll*384*128];  // [l][o][c]
__device__ __align__(16) float  g_NW1T[Ll*128*128];  // [l][o][c]
__device__ __align__(16) double g_Sd[BRr*128];
__device__ __align__(16) float  g_sel2[BB*NEe*2*128];
__device__ double g_sum[128];
__device__ double g_sumsq[128];
__device__ double g_a[128];
__device__ double g_c0[128];
__device__ int    g_mode;

__device__ __forceinline__ bool read_mask(const void* p, int i, int mode) {
    if (mode == 0) return ((const unsigned char*)p)[i] != 0;
    if (mode == 1) return ((const float*)p)[i] != 0.0f;
    return ((const int*)p)[i] != 0;
}

// ---- packed f32x2 helpers (lane-wise rounding identical to scalar FFMA) ----
__device__ __forceinline__ ull pack2(float a, float b) {
    ull r; asm("mov.b64 %0, {%1, %2};" : "=l"(r) : "f"(a), "f"(b)); return r;
}
__device__ __forceinline__ void unpack2(ull v, float& x, float& y) {
    asm("mov.b64 {%0, %1}, %2;" : "=f"(x), "=f"(y) : "l"(v));
}
__device__ __forceinline__ void fma2(ull& d, ull a, ull b) {
    asm("fma.rn.f32x2 %0, %1, %2, %3;" : "=l"(d) : "l"(a), "l"(b), "l"(d));
}
__device__ __forceinline__ float f4c(const float4& v, int i) {
    return i == 0 ? v.x : (i == 1 ? v.y : (i == 2 ? v.z : v.w));
}

__global__ void k_init(const unsigned char* __restrict__ mn) {
    int t = threadIdx.x;
    if (t < 128) { g_sum[t] = 0.0; g_sumsq[t] = 0.0; }
    if (t == 0) {
        bool b8 = false, f32 = false;
        for (int i = 0; i < 152; i++) {
            unsigned char v = mn[i];
            if ((i & 3) != 0 && v == 1) b8 = true;
            if ((i & 3) == 3 && v == 0x3f) f32 = true;
        }
        g_mode = b8 ? 0 : (f32 ? 1 : 2);
    }
}

__global__ void k_prep_w(const float* __restrict__ gc2, const float* __restrict__ gc3,
                         const float* __restrict__ ew1, const float* __restrict__ nw1) {
    int i = blockIdx.x * 256 + threadIdx.x;
    if (i < 49152) {
        int k = i / 384, c = i % 384;
        g_W2T[i] = gc2[c*128 + k];
        g_W3T[i] = gc3[c*128 + k];
    }
    if (i < 589824) {
        int l = i / 49152, rem = i % 49152;
        int o = rem / 128, c = rem % 128;
        g_EW1T[i] = ew1[l*49152 + c*384 + o];
    }
    if (i < 196608) {
        int l = i / 16384, rem = i % 16384;
        int o = rem / 128, c = rem % 128;
        g_NW1T[i] = nw1[l*16384 + c*128 + o];
    }
}

__global__ void k_prep_ps1(const float* __restrict__ x, const float* __restrict__ embw,
                           const float* __restrict__ gc1) {
    __shared__ float h0[Nn*NTt];
    int b = blockIdx.x, t = threadIdx.x;
    if (t < Nn*NTt) {
        int j = t / NTt, tt = t % NTt;
        float acc = 0.f;
        #pragma unroll
        for (int u = 0; u < NTt; u++) acc += x[(b*Nn + j)*NTt + u] * embw[tt*NTt + u];
        h0[t] = acc;
    }
    __syncthreads();
    if (t < 384) {
        for (int j = 0; j < Nn; j++) {
            float acc = 0.f;
            #pragma unroll
            for (int u = 0; u < NTt; u++) acc += h0[j*NTt + u] * gc1[t*NTt + u];
            g_PS1[(b*Nn + j)*384 + t] = acc;
        }
    }
}

// ---------------- fused RGCN (R7 configuration — best known) ----------------
__device__ __forceinline__ void block_einsum(const float* __restrict__ sA,
                                             const float* __restrict__ sS,
                                             float* __restrict__ sH,
                                             int tx, int ty, bool relu) {
    int rg = ty >> 1, cg = ty & 1;
    ull acc[10];
    #pragma unroll
    for (int r = 0; r < 10; r++) acc[r] = 0ull;
    #pragma unroll
    for (int e = 0; e < 3; e++) {
        const float* aE = sA + e*1600 + rg*10*40;
        const float* sE = sS + e*128 + cg*64 + tx*2;
        #pragma unroll 2
        for (int j = 0; j < 40; j += 4) {
            float4 a4[10];
            #pragma unroll
            for (int r = 0; r < 10; r++) a4[r] = *(const float4*)(aE + r*40 + j);
            #pragma unroll
            for (int dj = 0; dj < 4; dj++) {
                ull s2 = *(const ull*)(sE + (j + dj)*384);
                #pragma unroll
                for (int r = 0; r < 10; r++) {
                    float av = f4c(a4[r], dj);
                    fma2(acc[r], pack2(av, av), s2);
                }
            }
        }
    }
    #pragma unroll
    for (int r = 0; r < 10; r++) {
        float vx, vy;
        unpack2(acc[r], vx, vy);
        if (relu) { vx = fmaxf(vx, 0.f); vy = fmaxf(vy, 0.f); }
        *(ull*)(sH + (rg*10 + r)*128 + cg*64 + tx*2) = pack2(vx, vy);
    }
}

__device__ __forceinline__ void block_gemm(const float* __restrict__ WT,
                                           const float* __restrict__ sH,
                                           float* __restrict__ sS,
                                           int tx, int ty) {
    int rg = ty >> 1, cg = ty & 1;
    int colb = cg*192 + tx*2;
    const float* wb = WT + colb;
    const float* hb = sH + rg*10*128;
    ull acc[10][3];
    #pragma unroll
    for (int r = 0; r < 10; r++) { acc[r][0] = 0ull; acc[r][1] = 0ull; acc[r][2] = 0ull; }
    #pragma unroll 1
    for (int k = 0; k < 128; k += 4) {
        float4 h4[10];
        #pragma unroll
        for (int r = 0; r < 10; r++) h4[r] = *(const float4*)(hb + r*128 + k);
        #pragma unroll
        for (int dk = 0; dk < 4; dk++) {
            const float* wr = wb + (k + dk)*384;
            ull w0 = *(const ull*)(wr);
            ull w1 = *(const ull*)(wr + 64);
            ull w2v = *(const ull*)(wr + 128);
            #pragma unroll
            for (int r = 0; r < 10; r++) {
                float hv = f4c(h4[r], dk);
                ull hh = pack2(hv, hv);
                fma2(acc[r][0], hh, w0);
                fma2(acc[r][1], hh, w1);
                fma2(acc[r][2], hh, w2v);
            }
        }
    }
    #pragma unroll
    for (int r = 0; r < 10; r++) {
        float* ob = sS + (rg*10 + r)*384 + colb;
        *(ull*)(ob)       = acc[r][0];
        *(ull*)(ob + 64)  = acc[r][1];
        *(ull*)(ob + 128) = acc[r][2];
    }
}

__global__ __launch_bounds__(256, 2) void k_rgcn(
    const float* __restrict__ adj, const void* __restrict__ maskn,
    const void* __restrict__ maske, const int* __restrict__ isel)
{
    extern __shared__ float sm[];
    float* sA = sm;            // 3*40*40 = 4800
    float* sS = sm + 4800;     // 40*384 = 15360 (rows 38,39 stay zero)
    float* sH = sm + 20160;    // 40*128 = 5120
    int tid = threadIdx.x;
    int b = blockIdx.x / Rr, r = blockIdx.x % Rr;
    int mode = g_mode;

    for (int idx = tid; idx < 3*40*40; idx += 256) {
        int j = idx % 40;
        int i = (idx / 40) % 40;
        int e = idx / 1600;
        float v = 0.f;
        if (i < Nn && j < Nn && read_mask(maske, r*1444 + i*38 + j, mode))
            v = adj[((b*4 + e)*38 + i)*38 + j];
        sA[idx] = v;
    }
    for (int idx = tid; idx < 40*384; idx += 256) {
        int j = idx / 384, c = idx % 384;
        float v = 0.f;
        if (j < Nn && read_mask(maskn, r*38 + j, mode))
            v = g_PS1[(b*Nn + j)*384 + c];
        sS[idx] = v;
    }
    __syncthreads();

    int tx = tid & 31, ty = tid >> 5;
    block_einsum(sA, sS, sH, tx, ty, true);   __syncthreads();
    block_gemm(g_W2T, sH, sS, tx, ty);        __syncthreads();
    block_einsum(sA, sS, sH, tx, ty, true);   __syncthreads();
    block_gemm(g_W3T, sH, sS, tx, ty);        __syncthreads();
    block_einsum(sA, sS, sH, tx, ty, false);  __syncthreads();

    if (tid < 128) {
        double s = 0.0, sq = 0.0;
        for (int i = 0; i < Nn; i++) {
            double v = (double)sH[i*128 + tid];
            s += v; sq += v*v;
        }
        g_Sd[blockIdx.x*128 + tid] = s;
        atomicAdd(&g_sum[tid], s);
        atomicAdd(&g_sumsq[tid], sq);
    }
    if (r >= Nn) {
        int k = r - Nn;
        int o = tid & 127, sl = tid >> 7;
        int node = isel[k*2 + sl];
        g_sel2[((b*NEe + k)*2 + sl)*128 + o] = sH[node*128 + o];
    }
}

__global__ void k_stats(const float* __restrict__ gamma, const float* __restrict__ beta) {
    int o = threadIdx.x;
    if (o < 128) {
        const double cnt = (double)(BRr * Nn);
        double m   = g_sum[o] / cnt;
        double var = g_sumsq[o] / cnt - m*m;
        double inv = 1.0 / sqrt(var + 1e-5);
        double a = inv * (double)gamma[o];
        g_a[o]  = a;
        g_c0[o] = (double)beta[o] - m * a;
    }
}

// ---------------- merged flow kernel: edge CTAs [0,EBLKS), node CTAs [EBLKS, EBLKS+19) --
__global__ __launch_bounds__(256) void k_flow(
    const float* __restrict__ adj_deq, const float* __restrict__ eb1,
    const float* __restrict__ ew2, const float* __restrict__ eb2,
    const float* __restrict__ x_deq, const float* __restrict__ nb1,
    const float* __restrict__ nw2, const float* __restrict__ nb2,
    float* __restrict__ out)
{
    extern __shared__ float fsm[];
    int tid = threadIdx.x;
    int wrp = tid >> 5, lane = tid & 31;
    int rbase = wrp * 4;

    if (blockIdx.x < EBLKS) {
        // ================= EDGE PATH =================
        float* sg = fsm;               // 32*384
        float* wt = fsm + 12288;       // 64*128
        float* h  = fsm + 20480;       // 32*128
        float* lg = fsm + 24576;       // 32*4
        int* bi    = (int*)(fsm + 24704);
        int* P     = bi + 32;
        int* flags = bi + 64;
        int row0 = blockIdx.x * 32;

        for (int idx = tid; idx < 32*384; idx += 256) {
            int rl = idx / 384, o = idx % 384;
            int row = row0 + rl;
            double v = 0.0;
            if (row < EROWS) {
                int b = row / NEe, k = row % NEe;
                if (o < 256) {
                    int oo = o & 127;
                    v = (double)g_sel2[(b*NEe + k)*256 + o] * g_a[oo] + g_c0[oo];
                } else {
                    int oo = o - 256;
                    v = g_Sd[(b*Rr + Nn + k)*128 + oo] * g_a[oo] + 38.0 * g_c0[oo];
                }
            }
            sg[idx] = (float)v;
        }
        if (tid < 32) P[tid] = 0;

        for (int l = 0; l < Ll; l++) {
            ull acc[4][2];
            {
                float b0 = eb1[l*128 + lane*4+0], b1 = eb1[l*128 + lane*4+1];
                float b2 = eb1[l*128 + lane*4+2], b3 = eb1[l*128 + lane*4+3];
                ull p01 = pack2(b0, b1), p23 = pack2(b2, b3);
                #pragma unroll
                for (int r = 0; r < 4; r++) { acc[r][0] = p01; acc[r][1] = p23; }
            }
            for (int tile = 0; tile < 6; tile++) {
                __syncthreads();
                const float* src = g_EW1T + l*49152 + tile*8192;
                for (int i = tid*4; i < 8192; i += 1024)
                    *(float4*)(wt + i) = *(const float4*)(src + i);
                __syncthreads();
                #pragma unroll 2
                for (int oo = 0; oo < 64; oo += 4) {
                    float4 s4[4];
                    #pragma unroll
                    for (int r = 0; r < 4; r++)
                        s4[r] = *(const float4*)(sg + (rbase + r)*384 + tile*64 + oo);
                    #pragma unroll
                    for (int doo = 0; doo < 4; doo++) {
                        ulonglong2 w2 = *(const ulonglong2*)(wt + (oo + doo)*128 + lane*4);
                        #pragma unroll
                        for (int r = 0; r < 4; r++) {
                            float sv = f4c(s4[r], doo);
                            ull ss = pack2(sv, sv);
                            fma2(acc[r][0], ss, w2.x);
                            fma2(acc[r][1], ss, w2.y);
                        }
                    }
                }
            }
            #pragma unroll
            for (int r = 0; r < 4; r++) {
                float a0, a1, a2, a3;
                unpack2(acc[r][0], a0, a1);
                unpack2(acc[r][1], a2, a3);
                float* hp = h + (rbase + r)*128 + lane*4;
                hp[0] = tanhf(a0); hp[1] = tanhf(a1); hp[2] = tanhf(a2); hp[3] = tanhf(a3);
            }
            __syncthreads();
            if (tid < 128) {
                int rl = tid >> 2, t = tid & 3;
                const float* W2 = ew2 + (l*4 + t)*128;
                float a = eb2[l*4 + t];
                for (int c = 0; c < 128; c++) a = fmaf(h[rl*128 + c], W2[c], a);
                lg[rl*4 + t] = a;
            }
            __syncthreads();
            if (tid < 32) {
                float l0 = lg[tid*4], l1 = lg[tid*4+1], l2 = lg[tid*4+2], l3 = lg[tid*4+3];
                float best = l0; int bx = 0;
                if (l1 > best) { best = l1; bx = 1; }
                if (l2 > best) { best = l2; bx = 2; }
                if (l3 > best) { best = l3; bx = 3; }
                float second = -1e30f;
                if (bx != 0 && l0 > second) second = l0;
                if (bx != 1 && l1 > second) second = l1;
                if (bx != 2 && l2 > second) second = l2;
                if (bx != 3 && l3 > second) second = l3;
                bi[tid] = bx;
                flags[tid] = (best - second < TAU) && (row0 + tid < EROWS);
            }
            __syncthreads();
            // fp64 recompute (coalesced + shuffle-broadcast; o-ascending order preserved)
            for (int r = 0; r < 4; r++) {
                int rl = rbase + r;
                if (!flags[rl]) continue;
                int row = row0 + rl;
                int b = row / NEe, k = row % NEe;
                const float* W1 = g_EW1T + l*49152;
                double accd[4];
                #pragma unroll
                for (int q = 0; q < 4; q++) accd[q] = (double)eb1[l*128 + lane + 32*q];
                for (int ob = 0; ob < 384; ob += 32) {
                    int o = ob + lane;
                    double gv;
                    if (o < 256) {
                        int oo = o & 127;
                        gv = (double)g_sel2[(b*NEe + k)*256 + o] * g_a[oo] + g_c0[oo];
                    } else {
                        int oo = o - 256;
                        gv = g_Sd[(b*Rr + Nn + k)*128 + oo] * g_a[oo] + 38.0 * g_c0[oo];
                    }
                    #pragma unroll
                    for (int t2 = 0; t2 < 32; t2++) {
                        double gvb = __shfl_sync(0xffffffffu, gv, t2);
                        const float* wp = W1 + (ob + t2)*128 + lane;
                        accd[0] = fma(gvb, (double)wp[0],  accd[0]);
                        accd[1] = fma(gvb, (double)wp[32], accd[1]);
                        accd[2] = fma(gvb, (double)wp[64], accd[2]);
                        accd[3] = fma(gvb, (double)wp[96], accd[3]);
                    }
                }
                double hd[4];
                #pragma unroll
                for (int q = 0; q < 4; q++) hd[q] = tanh(accd[q]);
                double lgd[4];
                #pragma unroll
                for (int t = 0; t < 4; t++) {
                    const float* W2 = ew2 + (l*4 + t)*128;
                    double p = 0.0;
                    #pragma unroll
                    for (int q = 0; q < 4; q++) p = fma(hd[q], (double)W2[lane + 32*q], p);
                    #pragma unroll
                    for (int s = 16; s > 0; s >>= 1) p += __shfl_down_sync(0xffffffffu, p, s);
                    lgd[t] = p;
                }
                if (lane == 0) {
                    #pragma unroll
                    for (int t = 0; t < 4; t++) lgd[t] += (double)eb2[l*4 + t];
                    double best = lgd[0]; int bx = 0;
                    if (lgd[1] > best) { best = lgd[1]; bx = 1; }
                    if (lgd[2] > best) { best = lgd[2]; bx = 2; }
                    if (lgd[3] > best) { best = lgd[3]; bx = 3; }
                    bi[rl] = bx;
                }
            }
            __syncthreads();
            if (tid < 32) P[tid] += bi[tid];
        }
        __syncthreads();
        if (tid < 128) {
            int rl = tid >> 2, j = tid & 3;
            int row = row0 + rl;
            if (row < EROWS) {
                int p = P[rl] & 3;
                out[NROWS*NTt + row*4 + j] = adj_deq[row*4 + ((j - p + 4) & 3)];
            }
        }
    } else {
        // ================= NODE PATH =================
        float* sg = fsm;               // 32*128
        float* wt = fsm + 4096;        // 64*128
        float* h  = fsm + 12288;       // 32*128
        float* lg = fsm + 16384;       // 32*9
        int* bi    = (int*)(fsm + 16672);
        int* P     = bi + 32;
        int* flags = bi + 64;
        int row0 = (blockIdx.x - EBLKS) * 32;

        for (int idx = tid; idx < 32*128; idx += 256) {
            int rl = idx >> 7, o = idx & 127;
            int row = row0 + rl;
            int b = row / Nn, n = row % Nn;
            sg[idx] = (float)(g_Sd[(b*Rr + n)*128 + o] * g_a[o] + 38.0 * g_c0[o]);
        }
        if (tid < 32) P[tid] = 0;

        for (int l = 0; l < Ll; l++) {
            float acc[4][4];
            #pragma unroll
            for (int q = 0; q < 4; q++) {
                float bq = nb1[l*128 + lane*4 + q];
                acc[0][q] = bq; acc[1][q] = bq; acc[2][q] = bq; acc[3][q] = bq;
            }
            for (int tile = 0; tile < 2; tile++) {
                __syncthreads();
                const float* src = g_NW1T + l*16384 + tile*8192;
                for (int i = tid*4; i < 8192; i += 1024)
                    *(float4*)(wt + i) = *(const float4*)(src + i);
                __syncthreads();
                #pragma unroll 2
                for (int oo = 0; oo < 64; oo++) {
                    float4 w4 = *(const float4*)(wt + oo*128 + lane*4);
                    #pragma unroll
                    for (int r = 0; r < 4; r++) {
                        float s = sg[(rbase + r)*128 + tile*64 + oo];
                        acc[r][0] = fmaf(s, w4.x, acc[r][0]);
                        acc[r][1] = fmaf(s, w4.y, acc[r][1]);
                        acc[r][2] = fmaf(s, w4.z, acc[r][2]);
                        acc[r][3] = fmaf(s, w4.w, acc[r][3]);
                    }
                }
            }
            #pragma unroll
            for (int r = 0; r < 4; r++)
                #pragma unroll
                for (int q = 0; q < 4; q++)
                    h[(rbase + r)*128 + lane*4 + q] = tanhf(acc[r][q]);
            __syncthreads();
            for (int pp = tid; pp < 32*NTt; pp += 256) {
                int rl = pp / NTt, t = pp % NTt;
                const float* W2 = nw2 + (l*NTt + t)*128;
                float a = nb2[l*NTt + t];
                for (int c = 0; c < 128; c++) a = fmaf(h[rl*128 + c], W2[c], a);
                lg[rl*NTt + t] = a;
            }
            __syncthreads();
            if (tid < 32) {
                float best = lg[tid*NTt]; int bx = 0;
                #pragma unroll
                for (int t = 1; t < NTt; t++) {
                    float v = lg[tid*NTt + t];
                    if (v > best) { best = v; bx = t; }
                }
                float second = -1e30f;
                #pragma unroll
                for (int t = 0; t < NTt; t++) {
                    float v = lg[tid*NTt + t];
                    if (t != bx && v > second) second = v;
                }
                bi[tid] = bx;
                flags[tid] = (best - second < TAU);
            }
            __syncthreads();
            for (int r = 0; r < 4; r++) {
                int rl = rbase + r;
                if (!flags[rl]) continue;
                int row = row0 + rl;
                int b = row / Nn, n = row % Nn;
                const float* W1 = g_NW1T + l*16384;
                double accd[4];
                #pragma unroll
                for (int q = 0; q < 4; q++) accd[q] = (double)nb1[l*128 + lane + 32*q];
                for (int ob = 0; ob < 128; ob += 32) {
                    int o = ob + lane;
                    double gv = g_Sd[(b*Rr + n)*128 + o] * g_a[o] + 38.0 * g_c0[o];
                    #pragma unroll
                    for (int t2 = 0; t2 < 32; t2++) {
                        double gvb = __shfl_sync(0xffffffffu, gv, t2);
                        const float* wp = W1 + (ob + t2)*128 + lane;
                        accd[0] = fma(gvb, (double)wp[0],  accd[0]);
                        accd[1] = fma(gvb, (double)wp[32], accd[1]);
                        accd[2] = fma(gvb, (double)wp[64], accd[2]);
                        accd[3] = fma(gvb, (double)wp[96], accd[3]);
                    }
                }
                double hd[4];
                #pragma unroll
                for (int q = 0; q < 4; q++) hd[q] = tanh(accd[q]);
                double best = -1e300; int bx = 0;
                for (int t = 0; t < NTt; t++) {
                    const float* W2 = nw2 + (l*NTt + t)*128;
                    double p = 0.0;
                    #pragma unroll
                    for (int q = 0; q < 4; q++) p = fma(hd[q], (double)W2[lane + 32*q], p);
                    #pragma unroll
                    for (int s = 16; s > 0; s >>= 1) p += __shfl_down_sync(0xffffffffu, p, s);
                    if (lane == 0) {
                        p += (double)nb2[l*NTt + t];
                        if (p > best) { best = p; bx = t; }
                    }
                }
                if (lane == 0) bi[rl] = bx;
            }
            __syncthreads();
            if (tid < 32) P[tid] += bi[tid];
        }
        __syncthreads();
        for (int pp = tid; pp < 32*NTt; pp += 256) {
            int rl = pp / NTt, j = pp % NTt;
            int row = row0 + rl;
            int p = P[rl] % NTt;
            out[row*NTt + j] = x_deq[row*NTt + ((j - p + 18) % NTt)];
        }
    }
}

extern "C" void kernel_launch(void* const* d_in, const int* in_sizes, int n_in,
                              void* d_out, int out_size) {
    const float* x       = (const float*)d_in[0];
    const float* adj     = (const float*)d_in[1];
    const float* x_deq   = (const float*)d_in[2];
    const float* adj_deq = (const float*)d_in[3];
    const void*  mn      = d_in[4];
    const void*  me      = d_in[5];
    const int*   isel    = (const int*)d_in[6];
    const float* embw    = (const float*)d_in[7];
    const float* gc1     = (const float*)d_in[8];
    const float* gc2     = (const float*)d_in[9];
    const float* gc3     = (const float*)d_in[10];
    const float* gamma   = (const float*)d_in[11];
    const float* beta    = (const float*)d_in[12];
    const float* nw1     = (const float*)d_in[13];
    const float* nb1     = (const float*)d_in[14];
    const float* nw2     = (const float*)d_in[15];
    const float* nb2     = (const float*)d_in[16];
    const float* ew1     = (const float*)d_in[17];
    const float* eb1     = (const float*)d_in[18];
    const float* ew2     = (const float*)d_in[19];
    const float* eb2     = (const float*)d_in[20];
    float* out = (float*)d_out;

    cudaFuncSetAttribute(k_rgcn, cudaFuncAttributeMaxDynamicSharedMemorySize, 101376);
    cudaFuncSetAttribute(k_flow, cudaFuncAttributeMaxDynamicSharedMemorySize, 99200);

    k_init<<<1, 128>>>((const unsigned char*)mn);
    k_prep_w<<<2304, 256>>>(gc2, gc3, ew1, nw1);
    k_prep_ps1<<<16, 384>>>(x, embw, gc1);
    k_rgcn<<<BRr, 256, 101120>>>(adj, mn, me, isel);
    k_stats<<<1, 128>>>(gamma, beta);
    k_flow<<<EBLKS + 19, 256, 99200>>>(adj_deq, eb1, ew2, eb2,
                                       x_deq, nb1, nw2, nb2, out);
}

// round 14
// speedup vs baseline: 1.2367x; 1.0277x over previous
#include <cuda_runtime.h>
#include <math.h>

#define BB 16
#define Nn 38
#define NTt 9
#define NEe 703
#define Rr 741
#define BRr (BB*Rr)
#define Ll 12
#define EROWS (BB*NEe)   // 11248
#define NROWS (BB*Nn)    // 608
#define EBLKS 352
#define TAU 0.0015f

typedef unsigned long long ull;

// ---------------- static device scratch ----------------
__device__ __align__(16) float  g_PS1[BB*Nn*384];
__device__ __align__(16) float  g_W2T[128*384];
__device__ __align__(16) float  g_W3T[128*384];
__device__ __align__(16) float  g_EW1T[Ll*384*128];  // [l][o][c]
__device__ __align__(16) float  g_NW1T[Ll*128*128];  // [l][o][c]
__device__ __align__(16) double g_Sd[BRr*128];
__device__ __align__(16) float  g_sel2[BB*NEe*2*128];
__device__ double g_sum[128];
__device__ double g_sumsq[128];
__device__ double g_a[128];
__device__ double g_c0[128];
__device__ int    g_mode;

__device__ __forceinline__ bool read_mask(const void* p, int i, int mode) {
    if (mode == 0) return ((const unsigned char*)p)[i] != 0;
    if (mode == 1) return ((const float*)p)[i] != 0.0f;
    return ((const int*)p)[i] != 0;
}

// ---- packed f32x2 helpers (lane-wise rounding identical to scalar FFMA) ----
__device__ __forceinline__ ull pack2(float a, float b) {
    ull r; asm("mov.b64 %0, {%1, %2};" : "=l"(r) : "f"(a), "f"(b)); return r;
}
__device__ __forceinline__ void unpack2(ull v, float& x, float& y) {
    asm("mov.b64 {%0, %1}, %2;" : "=f"(x), "=f"(y) : "l"(v));
}
__device__ __forceinline__ void fma2(ull& d, ull a, ull b) {
    asm("fma.rn.f32x2 %0, %1, %2, %3;" : "=l"(d) : "l"(a), "l"(b), "l"(d));
}
__device__ __forceinline__ float f4c(const float4& v, int i) {
    return i == 0 ? v.x : (i == 1 ? v.y : (i == 2 ? v.z : v.w));
}

__global__ void k_init(const unsigned char* __restrict__ mn) {
    int t = threadIdx.x;
    if (t < 128) { g_sum[t] = 0.0; g_sumsq[t] = 0.0; }
    if (t == 0) {
        bool b8 = false, f32 = false;
        for (int i = 0; i < 152; i++) {
            unsigned char v = mn[i];
            if ((i & 3) != 0 && v == 1) b8 = true;
            if ((i & 3) == 3 && v == 0x3f) f32 = true;
        }
        g_mode = b8 ? 0 : (f32 ? 1 : 2);
    }
}

__global__ void k_prep_w(const float* __restrict__ gc2, const float* __restrict__ gc3,
                         const float* __restrict__ ew1, const float* __restrict__ nw1) {
    int i = blockIdx.x * 256 + threadIdx.x;
    if (i < 49152) {
        int k = i / 384, c = i % 384;
        g_W2T[i] = gc2[c*128 + k];
        g_W3T[i] = gc3[c*128 + k];
    }
    if (i < 589824) {
        int l = i / 49152, rem = i % 49152;
        int o = rem / 128, c = rem % 128;
        g_EW1T[i] = ew1[l*49152 + c*384 + o];
    }
    if (i < 196608) {
        int l = i / 16384, rem = i % 16384;
        int o = rem / 128, c = rem % 128;
        g_NW1T[i] = nw1[l*16384 + c*128 + o];
    }
}

__global__ void k_prep_ps1(const float* __restrict__ x, const float* __restrict__ embw,
                           const float* __restrict__ gc1) {
    __shared__ float h0[Nn*NTt];
    int b = blockIdx.x, t = threadIdx.x;
    if (t < Nn*NTt) {
        int j = t / NTt, tt = t % NTt;
        float acc = 0.f;
        #pragma unroll
        for (int u = 0; u < NTt; u++) acc += x[(b*Nn + j)*NTt + u] * embw[tt*NTt + u];
        h0[t] = acc;
    }
    __syncthreads();
    if (t < 384) {
        for (int j = 0; j < Nn; j++) {
            float acc = 0.f;
            #pragma unroll
            for (int u = 0; u < NTt; u++) acc += h0[j*NTt + u] * gc1[t*NTt + u];
            g_PS1[(b*Nn + j)*384 + t] = acc;
        }
    }
}

// ---------------- fused RGCN v5: R8 skeleton (59KB smem, 3 CTAs/SM) + 4-wide staging --
// einsum partial over one e: acc[r] += sum_j aE[row][j] * sE[j][col2]  (j ascending)
__device__ __forceinline__ void einsum_e(ull* acc, const float* __restrict__ aE,
                                         const float* __restrict__ sE,
                                         int tx, int rg, int cg) {
    const float* sp = sE + cg*64 + tx*2;
    const float* ap = aE + rg*10*40;
    #pragma unroll 1
    for (int j = 0; j < 40; j += 4) {
        ull s0 = *(const ull*)(sp + j*128);
        ull s1 = *(const ull*)(sp + (j+1)*128);
        ull s2 = *(const ull*)(sp + (j+2)*128);
        ull s3 = *(const ull*)(sp + (j+3)*128);
        #pragma unroll
        for (int rb = 0; rb < 10; rb += 2) {
            float4 aa = *(const float4*)(ap + rb*40 + j);
            float4 ac = *(const float4*)(ap + (rb+1)*40 + j);
            fma2(acc[rb],   pack2(aa.x, aa.x), s0);
            fma2(acc[rb],   pack2(aa.y, aa.y), s1);
            fma2(acc[rb],   pack2(aa.z, aa.z), s2);
            fma2(acc[rb],   pack2(aa.w, aa.w), s3);
            fma2(acc[rb+1], pack2(ac.x, ac.x), s0);
            fma2(acc[rb+1], pack2(ac.y, ac.y), s1);
            fma2(acc[rb+1], pack2(ac.z, ac.z), s2);
            fma2(acc[rb+1], pack2(ac.w, ac.w), s3);
        }
    }
}

// gemm slice: sE[j][c] = sum_k sH[j][k] * WTe[k*384 + c]   (k ascending; WTe = WT + e*128)
__device__ __forceinline__ void gemm_e(const float* __restrict__ WTe,
                                       const float* __restrict__ sH,
                                       float* __restrict__ sE,
                                       int tx, int rg, int cg) {
    const float* wb = WTe + cg*64 + tx*2;
    const float* hb = sH + rg*10*128;
    ull acc[10];
    #pragma unroll
    for (int r = 0; r < 10; r++) acc[r] = 0ull;
    #pragma unroll 1
    for (int k = 0; k < 128; k += 4) {
        ull w0 = *(const ull*)(wb + k*384);
        ull w1 = *(const ull*)(wb + (k+1)*384);
        ull w2 = *(const ull*)(wb + (k+2)*384);
        ull w3 = *(const ull*)(wb + (k+3)*384);
        #pragma unroll
        for (int rb = 0; rb < 10; rb += 2) {
            float4 ha = *(const float4*)(hb + rb*128 + k);
            float4 hc = *(const float4*)(hb + (rb+1)*128 + k);
            fma2(acc[rb],   pack2(ha.x, ha.x), w0);
            fma2(acc[rb],   pack2(ha.y, ha.y), w1);
            fma2(acc[rb],   pack2(ha.z, ha.z), w2);
            fma2(acc[rb],   pack2(ha.w, ha.w), w3);
            fma2(acc[rb+1], pack2(hc.x, hc.x), w0);
            fma2(acc[rb+1], pack2(hc.y, hc.y), w1);
            fma2(acc[rb+1], pack2(hc.z, hc.z), w2);
            fma2(acc[rb+1], pack2(hc.w, hc.w), w3);
        }
    }
    #pragma unroll
    for (int r = 0; r < 10; r++)
        *(ull*)(sE + (rg*10 + r)*128 + cg*64 + tx*2) = acc[r];
}

__device__ __forceinline__ void store_sH(const ull* acc, float* __restrict__ sH,
                                         int tx, int rg, int cg, bool relu) {
    #pragma unroll
    for (int r = 0; r < 10; r++) {
        float vx, vy;
        unpack2(acc[r], vx, vy);
        if (relu) { vx = fmaxf(vx, 0.f); vy = fmaxf(vy, 0.f); }
        *(ull*)(sH + (rg*10 + r)*128 + cg*64 + tx*2) = pack2(vx, vy);
    }
}

__global__ __launch_bounds__(256, 3) void k_rgcn(
    const float* __restrict__ adj, const void* __restrict__ maskn,
    const void* __restrict__ maske, const int* __restrict__ isel)
{
    extern __shared__ float sm[];
    float* sA = sm;            // 3*40*40 = 4800
    float* sH = sm + 4800;     // 40*128 = 5120
    float* sE = sm + 9920;     // 40*128 = 5120   (total 15040 floats = 58.75KB)
    int tid = threadIdx.x;
    int b = blockIdx.x / Rr, r = blockIdx.x % Rr;
    int mode = g_mode;

    for (int idx = tid; idx < 3*40*40; idx += 256) {
        int j = idx % 40;
        int i = (idx / 40) % 40;
        int e = idx / 1600;
        float v = 0.f;
        if (i < Nn && j < Nn && read_mask(maske, r*1444 + i*38 + j, mode))
            v = adj[((b*4 + e)*38 + i)*38 + j];
        sA[idx] = v;
    }

    int tx = tid & 31, ty = tid >> 5;
    int rg = ty >> 1, cg = ty & 1;

    // ---- layer 1: einsum over masked PS1 e-slices ----
    ull acc1[10];
    #pragma unroll
    for (int q = 0; q < 10; q++) acc1[q] = 0ull;
    for (int e = 0; e < 3; e++) {
        __syncthreads();   // sA ready (e=0) / prior einsum done reading sE (e>0)
        for (int idx = tid; idx < 40*128; idx += 256) {
            int j = idx >> 7, c = idx & 127;
            float v = 0.f;
            if (j < Nn && read_mask(maskn, r*38 + j, mode))
                v = g_PS1[(b*Nn + j)*384 + e*128 + c];
            sE[idx] = v;
        }
        __syncthreads();
        einsum_e(acc1, sA + e*1600, sE, tx, rg, cg);
    }
    store_sH(acc1, sH, tx, rg, cg, true);

    // ---- layer 2 ----
    ull acc2[10];
    #pragma unroll
    for (int q = 0; q < 10; q++) acc2[q] = 0ull;
    for (int e = 0; e < 3; e++) {
        __syncthreads();   // sH stores visible (e=0) / prior einsum done with sE (e>0)
        gemm_e(g_W2T + e*128, sH, sE, tx, rg, cg);
        __syncthreads();
        einsum_e(acc2, sA + e*1600, sE, tx, rg, cg);
    }
    store_sH(acc2, sH, tx, rg, cg, true);   // all gemm reads of sH completed before this

    // ---- layer 3 ----
    ull acc3[10];
    #pragma unroll
    for (int q = 0; q < 10; q++) acc3[q] = 0ull;
    for (int e = 0; e < 3; e++) {
        __syncthreads();
        gemm_e(g_W3T + e*128, sH, sE, tx, rg, cg);
        __syncthreads();
        einsum_e(acc3, sA + e*1600, sE, tx, rg, cg);
    }
    store_sH(acc3, sH, tx, rg, cg, false);
    __syncthreads();

    if (tid < 128) {
        double s = 0.0, sq = 0.0;
        for (int i = 0; i < Nn; i++) {
            double v = (double)sH[i*128 + tid];
            s += v; sq += v*v;
        }
        g_Sd[blockIdx.x*128 + tid] = s;
        atomicAdd(&g_sum[tid], s);
        atomicAdd(&g_sumsq[tid], sq);
    }
    if (r >= Nn) {
        int k = r - Nn;
        int o = tid & 127, sl = tid >> 7;
        int node = isel[k*2 + sl];
        g_sel2[((b*NEe + k)*2 + sl)*128 + o] = sH[node*128 + o];
    }
}

__global__ void k_stats(const float* __restrict__ gamma, const float* __restrict__ beta) {
    int o = threadIdx.x;
    if (o < 128) {
        const double cnt = (double)(BRr * Nn);
        double m   = g_sum[o] / cnt;
        double var = g_sumsq[o] / cnt - m*m;
        double inv = 1.0 / sqrt(var + 1e-5);
        double a = inv * (double)gamma[o];
        g_a[o]  = a;
        g_c0[o] = (double)beta[o] - m * a;
    }
}

// ---------------- merged flow kernel: edge CTAs [0,EBLKS), node CTAs [EBLKS, EBLKS+19) --
__global__ __launch_bounds__(256) void k_flow(
    const float* __restrict__ adj_deq, const float* __restrict__ eb1,
    const float* __restrict__ ew2, const float* __restrict__ eb2,
    const float* __restrict__ x_deq, const float* __restrict__ nb1,
    const float* __restrict__ nw2, const float* __restrict__ nb2,
    float* __restrict__ out)
{
    extern __shared__ float fsm[];
    int tid = threadIdx.x;
    int wrp = tid >> 5, lane = tid & 31;
    int rbase = wrp * 4;

    if (blockIdx.x < EBLKS) {
        // ================= EDGE PATH =================
        float* sg = fsm;               // 32*384
        float* wt = fsm + 12288;       // 64*128
        float* h  = fsm + 20480;       // 32*128
        float* lg = fsm + 24576;       // 32*4
        int* bi    = (int*)(fsm + 24704);
        int* P     = bi + 32;
        int* flags = bi + 64;
        int row0 = blockIdx.x * 32;

        for (int idx = tid; idx < 32*384; idx += 256) {
            int rl = idx / 384, o = idx % 384;
            int row = row0 + rl;
            double v = 0.0;
            if (row < EROWS) {
                int b = row / NEe, k = row % NEe;
                if (o < 256) {
                    int oo = o & 127;
                    v = (double)g_sel2[(b*NEe + k)*256 + o] * g_a[oo] + g_c0[oo];
                } else {
                    int oo = o - 256;
                    v = g_Sd[(b*Rr + Nn + k)*128 + oo] * g_a[oo] + 38.0 * g_c0[oo];
                }
            }
            sg[idx] = (float)v;
        }
        if (tid < 32) P[tid] = 0;

        for (int l = 0; l < Ll; l++) {
            ull acc[4][2];
            {
                float b0 = eb1[l*128 + lane*4+0], b1 = eb1[l*128 + lane*4+1];
                float b2 = eb1[l*128 + lane*4+2], b3 = eb1[l*128 + lane*4+3];
                ull p01 = pack2(b0, b1), p23 = pack2(b2, b3);
                #pragma unroll
                for (int r = 0; r < 4; r++) { acc[r][0] = p01; acc[r][1] = p23; }
            }
            for (int tile = 0; tile < 6; tile++) {
                __syncthreads();
                const float* src = g_EW1T + l*49152 + tile*8192;
                for (int i = tid*4; i < 8192; i += 1024)
                    *(float4*)(wt + i) = *(const float4*)(src + i);
                __syncthreads();
                #pragma unroll 2
                for (int oo = 0; oo < 64; oo += 4) {
                    float4 s4[4];
                    #pragma unroll
                    for (int r = 0; r < 4; r++)
                        s4[r] = *(const float4*)(sg + (rbase + r)*384 + tile*64 + oo);
                    #pragma unroll
                    for (int doo = 0; doo < 4; doo++) {
                        ulonglong2 w2 = *(const ulonglong2*)(wt + (oo + doo)*128 + lane*4);
                        #pragma unroll
                        for (int r = 0; r < 4; r++) {
                            float sv = f4c(s4[r], doo);
                            ull ss = pack2(sv, sv);
                            fma2(acc[r][0], ss, w2.x);
                            fma2(acc[r][1], ss, w2.y);
                        }
                    }
                }
            }
            #pragma unroll
            for (int r = 0; r < 4; r++) {
                float a0, a1, a2, a3;
                unpack2(acc[r][0], a0, a1);
                unpack2(acc[r][1], a2, a3);
                float* hp = h + (rbase + r)*128 + lane*4;
                hp[0] = tanhf(a0); hp[1] = tanhf(a1); hp[2] = tanhf(a2); hp[3] = tanhf(a3);
            }
            __syncthreads();
            if (tid < 128) {
                int rl = tid >> 2, t = tid & 3;
                const float* W2 = ew2 + (l*4 + t)*128;
                float a = eb2[l*4 + t];
                for (int c = 0; c < 128; c++) a = fmaf(h[rl*128 + c], W2[c], a);
                lg[rl*4 + t] = a;
            }
            __syncthreads();
            if (tid < 32) {
                float l0 = lg[tid*4], l1 = lg[tid*4+1], l2 = lg[tid*4+2], l3 = lg[tid*4+3];
                float best = l0; int bx = 0;
                if (l1 > best) { best = l1; bx = 1; }
                if (l2 > best) { best = l2; bx = 2; }
                if (l3 > best) { best = l3; bx = 3; }
                float second = -1e30f;
                if (bx != 0 && l0 > second) second = l0;
                if (bx != 1 && l1 > second) second = l1;
                if (bx != 2 && l2 > second) second = l2;
                if (bx != 3 && l3 > second) second = l3;
                bi[tid] = bx;
                flags[tid] = (best - second < TAU) && (row0 + tid < EROWS);
            }
            __syncthreads();
            // fp64 recompute (coalesced + shuffle-broadcast; o-ascending order preserved)
            for (int r = 0; r < 4; r++) {
                int rl = rbase + r;
                if (!flags[rl]) continue;
                int row = row0 + rl;
                int b = row / NEe, k = row % NEe;
                const float* W1 = g_EW1T + l*49152;
                double accd[4];
                #pragma unroll
                for (int q = 0; q < 4; q++) accd[q] = (double)eb1[l*128 + lane + 32*q];
                for (int ob = 0; ob < 384; ob += 32) {
                    int o = ob + lane;
                    double gv;
                    if (o < 256) {
                        int oo = o & 127;
                        gv = (double)g_sel2[(b*NEe + k)*256 + o] * g_a[oo] + g_c0[oo];
                    } else {
                        int oo = o - 256;
                        gv = g_Sd[(b*Rr + Nn + k)*128 + oo] * g_a[oo] + 38.0 * g_c0[oo];
                    }
                    #pragma unroll
                    for (int t2 = 0; t2 < 32; t2++) {
                        double gvb = __shfl_sync(0xffffffffu, gv, t2);
                        const float* wp = W1 + (ob + t2)*128 + lane;
                        accd[0] = fma(gvb, (double)wp[0],  accd[0]);
                        accd[1] = fma(gvb, (double)wp[32], accd[1]);
                        accd[2] = fma(gvb, (double)wp[64], accd[2]);
                        accd[3] = fma(gvb, (double)wp[96], accd[3]);
                    }
                }
                double hd[4];
                #pragma unroll
                for (int q = 0; q < 4; q++) hd[q] = tanh(accd[q]);
                double lgd[4];
                #pragma unroll
                for (int t = 0; t < 4; t++) {
                    const float* W2 = ew2 + (l*4 + t)*128;
                    double p = 0.0;
                    #pragma unroll
                    for (int q = 0; q < 4; q++) p = fma(hd[q], (double)W2[lane + 32*q], p);
                    #pragma unroll
                    for (int s = 16; s > 0; s >>= 1) p += __shfl_down_sync(0xffffffffu, p, s);
                    lgd[t] = p;
                }
                if (lane == 0) {
                    #pragma unroll
                    for (int t = 0; t < 4; t++) lgd[t] += (double)eb2[l*4 + t];
                    double best = lgd[0]; int bx = 0;
                    if (lgd[1] > best) { best = lgd[1]; bx = 1; }
                    if (lgd[2] > best) { best = lgd[2]; bx = 2; }
                    if (lgd[3] > best) { best = lgd[3]; bx = 3; }
                    bi[rl] = bx;
                }
            }
            __syncthreads();
            if (tid < 32) P[tid] += bi[tid];
        }
        __syncthreads();
        if (tid < 128) {
            int rl = tid >> 2, j = tid & 3;
            int row = row0 + rl;
            if (row < EROWS) {
                int p = P[rl] & 3;
                out[NROWS*NTt + row*4 + j] = adj_deq[row*4 + ((j - p + 4) & 3)];
            }
        }
    } else {
        // ================= NODE PATH =================
        float* sg = fsm;               // 32*128
        float* wt = fsm + 4096;        // 64*128
        float* h  = fsm + 12288;       // 32*128
        float* lg = fsm + 16384;       // 32*9
        int* bi    = (int*)(fsm + 16672);
        int* P     = bi + 32;
        int* flags = bi + 64;
        int row0 = (blockIdx.x - EBLKS) * 32;

        for (int idx = tid; idx < 32*128; idx += 256) {
            int rl = idx >> 7, o = idx & 127;
            int row = row0 + rl;
            int b = row / Nn, n = row % Nn;
            sg[idx] = (float)(g_Sd[(b*Rr + n)*128 + o] * g_a[o] + 38.0 * g_c0[o]);
        }
        if (tid < 32) P[tid] = 0;

        for (int l = 0; l < Ll; l++) {
            float acc[4][4];
            #pragma unroll
            for (int q = 0; q < 4; q++) {
                float bq = nb1[l*128 + lane*4 + q];
                acc[0][q] = bq; acc[1][q] = bq; acc[2][q] = bq; acc[3][q] = bq;
            }
            for (int tile = 0; tile < 2; tile++) {
                __syncthreads();
                const float* src = g_NW1T + l*16384 + tile*8192;
                for (int i = tid*4; i < 8192; i += 1024)
                    *(float4*)(wt + i) = *(const float4*)(src + i);
                __syncthreads();
                #pragma unroll 2
                for (int oo = 0; oo < 64; oo++) {
                    float4 w4 = *(const float4*)(wt + oo*128 + lane*4);
                    #pragma unroll
                    for (int r = 0; r < 4; r++) {
                        float s = sg[(rbase + r)*128 + tile*64 + oo];
                        acc[r][0] = fmaf(s, w4.x, acc[r][0]);
                        acc[r][1] = fmaf(s, w4.y, acc[r][1]);
                        acc[r][2] = fmaf(s, w4.z, acc[r][2]);
                        acc[r][3] = fmaf(s, w4.w, acc[r][3]);
                    }
                }
            }
            #pragma unroll
            for (int r = 0; r < 4; r++)
                #pragma unroll
                for (int q = 0; q < 4; q++)
                    h[(rbase + r)*128 + lane*4 + q] = tanhf(acc[r][q]);
            __syncthreads();
            for (int pp = tid; pp < 32*NTt; pp += 256) {
                int rl = pp / NTt, t = pp % NTt;
                const float* W2 = nw2 + (l*NTt + t)*128;
                float a = nb2[l*NTt + t];
                for (int c = 0; c < 128; c++) a = fmaf(h[rl*128 + c], W2[c], a);
                lg[rl*NTt + t] = a;
            }
            __syncthreads();
            if (tid < 32) {
                float best = lg[tid*NTt]; int bx = 0;
                #pragma unroll
                for (int t = 1; t < NTt; t++) {
                    float v = lg[tid*NTt + t];
                    if (v > best) { best = v; bx = t; }
                }
                float second = -1e30f;
                #pragma unroll
                for (int t = 0; t < NTt; t++) {
                    float v = lg[tid*NTt + t];
                    if (t != bx && v > second) second = v;
                }
                bi[tid] = bx;
                flags[tid] = (best - second < TAU);
            }
            __syncthreads();
            for (int r = 0; r < 4; r++) {
                int rl = rbase + r;
                if (!flags[rl]) continue;
                int row = row0 + rl;
                int b = row / Nn, n = row % Nn;
                const float* W1 = g_NW1T + l*16384;
                double accd[4];
                #pragma unroll
                for (int q = 0; q < 4; q++) accd[q] = (double)nb1[l*128 + lane + 32*q];
                for (int ob = 0; ob < 128; ob += 32) {
                    int o = ob + lane;
                    double gv = g_Sd[(b*Rr + n)*128 + o] * g_a[o] + 38.0 * g_c0[o];
                    #pragma unroll
                    for (int t2 = 0; t2 < 32; t2++) {
                        double gvb = __shfl_sync(0xffffffffu, gv, t2);
                        const float* wp = W1 + (ob + t2)*128 + lane;
                        accd[0] = fma(gvb, (double)wp[0],  accd[0]);
                        accd[1] = fma(gvb, (double)wp[32], accd[1]);
                        accd[2] = fma(gvb, (double)wp[64], accd[2]);
                        accd[3] = fma(gvb, (double)wp[96], accd[3]);
                    }
                }
                double hd[4];
                #pragma unroll
                for (int q = 0; q < 4; q++) hd[q] = tanh(accd[q]);
                double best = -1e300; int bx = 0;
                for (int t = 0; t < NTt; t++) {
                    const float* W2 = nw2 + (l*NTt + t)*128;
                    double p = 0.0;
                    #pragma unroll
                    for (int q = 0; q < 4; q++) p = fma(hd[q], (double)W2[lane + 32*q], p);
                    #pragma unroll
                    for (int s = 16; s > 0; s >>= 1) p += __shfl_down_sync(0xffffffffu, p, s);
                    if (lane == 0) {
                        p += (double)nb2[l*NTt + t];
                        if (p > best) { best = p; bx = t; }
                    }
                }
                if (lane == 0) bi[rl] = bx;
            }
            __syncthreads();
            if (tid < 32) P[tid] += bi[tid];
        }
        __syncthreads();
        for (int pp = tid; pp < 32*NTt; pp += 256) {
            int rl = pp / NTt, j = pp % NTt;
            int row = row0 + rl;
            int p = P[rl] % NTt;
            out[row*NTt + j] = x_deq[row*NTt + ((j - p + 18) % NTt)];
        }
    }
}

extern "C" void kernel_launch(void* const* d_in, const int* in_sizes, int n_in,
                              void* d_out, int out_size) {
    const float* x       = (const float*)d_in[0];
    const float* adj     = (const float*)d_in[1];
    const float* x_deq   = (const float*)d_in[2];
    const float* adj_deq = (const float*)d_in[3];
    const void*  mn      = d_in[4];
    const void*  me      = d_in[5];
    const int*   isel    = (const int*)d_in[6];
    const float* embw    = (const float*)d_in[7];
    const float* gc1     = (const float*)d_in[8];
    const float* gc2     = (const float*)d_in[9];
    const float* gc3     = (const float*)d_in[10];
    const float* gamma   = (const float*)d_in[11];
    const float* beta    = (const float*)d_in[12];
    const float* nw1     = (const float*)d_in[13];
    const float* nb1     = (const float*)d_in[14];
    const float* nw2     = (const float*)d_in[15];
    const float* nb2     = (const float*)d_in[16];
    const float* ew1     = (const float*)d_in[17];
    const float* eb1     = (const float*)d_in[18];
    const float* ew2     = (const float*)d_in[19];
    const float* eb2     = (const float*)d_in[20];
    float* out = (float*)d_out;

    cudaFuncSetAttribute(k_rgcn, cudaFuncAttributeMaxDynamicSharedMemorySize, 61440);
    cudaFuncSetAttribute(k_flow, cudaFuncAttributeMaxDynamicSharedMemorySize, 99200);

    k_init<<<1, 128>>>((const unsigned char*)mn);
    k_prep_w<<<2304, 256>>>(gc2, gc3, ew1, nw1);
    k_prep_ps1<<<16, 384>>>(x, embw, gc1);
    k_rgcn<<<BRr, 256, 60160>>>(adj, mn, me, isel);
    k_stats<<<1, 128>>>(gamma, beta);
    k_flow<<<EBLKS + 19, 256, 99200>>>(adj_deq, eb1, ew2, eb2,
                                       x_deq, nb1, nw2, nb2, out);
}